// round 1
// baseline (speedup 1.0000x reference)
#include <cuda_runtime.h>
#include <cstdint>

// CZ gate on qubits (i, j) of an NQUBIT-wide state, batched.
// out[b, idx] = x[b, idx] * (-1)^( bit_{n-1-i}(idx) & bit_{n-1-j}(idx) )
// Pure streaming: 128-bit vectorized load/store, sign via XOR of fp32 sign bit.

static constexpr int NQUBIT = 22;
static constexpr uint32_t DIM = 1u << NQUBIT;          // 4194304
static constexpr uint32_t DIM_VEC_MASK = (DIM >> 2) - 1; // mask for float4 index within one batch row

__global__ void __launch_bounds__(256, 8)
cz_kernel(const float4* __restrict__ x,
          const int* __restrict__ pi,
          const int* __restrict__ pj,
          float4* __restrict__ out,
          int n_vec)
{
    int idx = blockIdx.x * blockDim.x + threadIdx.x;
    if (idx >= n_vec) return;

    // i, j are scalars in device memory; broadcast L2 hit, negligible.
    const int i = __ldg(pi);
    const int j = __ldg(pj);
    const uint32_t bi = (uint32_t)(NQUBIT - 1 - i);
    const uint32_t bj = (uint32_t)(NQUBIT - 1 - j);

    float4 v = x[idx];

    // element index within the 2^22 state vector (batch dim drops out via mask)
    const uint32_t base = ((uint32_t)idx & DIM_VEC_MASK) << 2;

    uint32_t e0 = base + 0u, e1 = base + 1u, e2 = base + 2u, e3 = base + 3u;
    uint32_t s0 = (((e0 >> bi) & (e0 >> bj)) & 1u) << 31;
    uint32_t s1 = (((e1 >> bi) & (e1 >> bj)) & 1u) << 31;
    uint32_t s2 = (((e2 >> bi) & (e2 >> bj)) & 1u) << 31;
    uint32_t s3 = (((e3 >> bi) & (e3 >> bj)) & 1u) << 31;

    v.x = __uint_as_float(__float_as_uint(v.x) ^ s0);
    v.y = __uint_as_float(__float_as_uint(v.y) ^ s1);
    v.z = __uint_as_float(__float_as_uint(v.z) ^ s2);
    v.w = __uint_as_float(__float_as_uint(v.w) ^ s3);

    out[idx] = v;
}

extern "C" void kernel_launch(void* const* d_in, const int* in_sizes, int n_in,
                              void* d_out, int out_size)
{
    const float4* x  = (const float4*)d_in[0];
    const int*    pi = (const int*)d_in[1];
    const int*    pj = (const int*)d_in[2];
    float4*       out = (float4*)d_out;

    const int n_vec = out_size / 4;               // total float4s (8 * 2^22 / 4)
    const int threads = 256;
    const int blocks = (n_vec + threads - 1) / threads;
    cz_kernel<<<blocks, threads>>>(x, pi, pj, out, n_vec);
}

// round 2
// speedup vs baseline: 1.0021x; 1.0021x over previous
#include <cuda_runtime.h>
#include <cstdint>

// CZ gate on qubits (i, j) of an NQUBIT-wide state, batched.
// out[b, idx] = x[b, idx] * (-1)^( bit_{n-1-i}(idx) & bit_{n-1-j}(idx) )
// Streaming kernel: 4 independent float4 loads per thread (MLP=4),
// evict-first cache hints, sign applied via XOR on the fp32 sign bit.

static constexpr int NQUBIT = 22;
static constexpr uint32_t DIM = 1u << NQUBIT;            // 4194304 elements per batch row
static constexpr uint32_t DIM_VEC_MASK = (DIM >> 2) - 1; // float4-index mask within a row
static constexpr int VPT = 4;                            // float4s per thread

__device__ __forceinline__ float4 apply_sign(float4 v, uint32_t vec_idx,
                                             uint32_t bi, uint32_t bj)
{
    const uint32_t base = (vec_idx & DIM_VEC_MASK) << 2;
    uint32_t e0 = base, e1 = base + 1u, e2 = base + 2u, e3 = base + 3u;
    uint32_t s0 = (((e0 >> bi) & (e0 >> bj)) & 1u) << 31;
    uint32_t s1 = (((e1 >> bi) & (e1 >> bj)) & 1u) << 31;
    uint32_t s2 = (((e2 >> bi) & (e2 >> bj)) & 1u) << 31;
    uint32_t s3 = (((e3 >> bi) & (e3 >> bj)) & 1u) << 31;
    v.x = __uint_as_float(__float_as_uint(v.x) ^ s0);
    v.y = __uint_as_float(__float_as_uint(v.y) ^ s1);
    v.z = __uint_as_float(__float_as_uint(v.z) ^ s2);
    v.w = __uint_as_float(__float_as_uint(v.w) ^ s3);
    return v;
}

__global__ void __launch_bounds__(256, 8)
cz_kernel(const float4* __restrict__ x,
          const int* __restrict__ pi,
          const int* __restrict__ pj,
          float4* __restrict__ out,
          int n_vec)
{
    const int tile = blockDim.x * VPT;                 // 1024 float4s per block
    const int base_idx = blockIdx.x * tile + threadIdx.x;

    const int i = __ldg(pi);
    const int j = __ldg(pj);
    const uint32_t bi = (uint32_t)(NQUBIT - 1 - i);
    const uint32_t bj = (uint32_t)(NQUBIT - 1 - j);

    // Fast path: full tile in range (always true here since n_vec % 1024 == 0,
    // but keep a guarded path for generality).
    if (base_idx + 3 * 256 < n_vec && (blockIdx.x + 1) * tile <= n_vec) {
        // Batch all 4 loads first: MLP=4 outstanding LDG.128 per thread.
        float4 v0 = __ldcs(&x[base_idx + 0 * 256]);
        float4 v1 = __ldcs(&x[base_idx + 1 * 256]);
        float4 v2 = __ldcs(&x[base_idx + 2 * 256]);
        float4 v3 = __ldcs(&x[base_idx + 3 * 256]);

        v0 = apply_sign(v0, (uint32_t)(base_idx + 0 * 256), bi, bj);
        v1 = apply_sign(v1, (uint32_t)(base_idx + 1 * 256), bi, bj);
        v2 = apply_sign(v2, (uint32_t)(base_idx + 2 * 256), bi, bj);
        v3 = apply_sign(v3, (uint32_t)(base_idx + 3 * 256), bi, bj);

        __stcs(&out[base_idx + 0 * 256], v0);
        __stcs(&out[base_idx + 1 * 256], v1);
        __stcs(&out[base_idx + 2 * 256], v2);
        __stcs(&out[base_idx + 3 * 256], v3);
    } else {
        #pragma unroll
        for (int k = 0; k < VPT; k++) {
            int idx = base_idx + k * 256;
            if (idx < n_vec) {
                float4 v = __ldcs(&x[idx]);
                v = apply_sign(v, (uint32_t)idx, bi, bj);
                __stcs(&out[idx], v);
            }
        }
    }
}

extern "C" void kernel_launch(void* const* d_in, const int* in_sizes, int n_in,
                              void* d_out, int out_size)
{
    const float4* x   = (const float4*)d_in[0];
    const int*    pi  = (const int*)d_in[1];
    const int*    pj  = (const int*)d_in[2];
    float4*       out = (float4*)d_out;

    const int n_vec = out_size / 4;                    // total float4s
    const int threads = 256;
    const int tile = threads * VPT;                    // 1024
    const int blocks = (n_vec + tile - 1) / tile;      // 8192
    cz_kernel<<<blocks, threads>>>(x, pi, pj, out, n_vec);
}

// round 3
// speedup vs baseline: 1.0301x; 1.0279x over previous
#include <cuda_runtime.h>
#include <cstdint>

// CZ gate on qubits (i, j) of an NQUBIT-wide state, batched.
// out[b, e] = x[b, e] * (-1)^( bit_{n-1-i}(e) & bit_{n-1-j}(e) )
// Streaming kernel: 8 independent float4 loads per thread (128 B bursts),
// evict-first cache hints, one sign test per float4 when both wire bits
// sit above the intra-vector bits (bi,bj >= 2).

static constexpr int NQUBIT = 22;
static constexpr uint32_t DIM = 1u << NQUBIT;            // elements per batch row
static constexpr uint32_t DIM_VEC_MASK = (DIM >> 2) - 1; // float4-index mask within a row
static constexpr int THREADS = 256;
static constexpr int VPT = 8;                            // float4s per thread
static constexpr int TILE = THREADS * VPT;               // 2048 float4s per block

__device__ __forceinline__ float4 xor_sign4(float4 v, uint32_t s)
{
    v.x = __uint_as_float(__float_as_uint(v.x) ^ s);
    v.y = __uint_as_float(__float_as_uint(v.y) ^ s);
    v.z = __uint_as_float(__float_as_uint(v.z) ^ s);
    v.w = __uint_as_float(__float_as_uint(v.w) ^ s);
    return v;
}

__device__ __forceinline__ float4 apply_sign_general(float4 v, uint32_t vec_idx,
                                                     uint32_t bi, uint32_t bj)
{
    const uint32_t base = (vec_idx & DIM_VEC_MASK) << 2;
    #pragma unroll
    for (int e = 0; e < 4; e++) {
        uint32_t idx = base + (uint32_t)e;
        uint32_t s = (((idx >> bi) & (idx >> bj)) & 1u) << 31;
        reinterpret_cast<uint32_t*>(&v)[e] ^= s;
    }
    return v;
}

__global__ void __launch_bounds__(THREADS)
cz_kernel(const float4* __restrict__ x,
          const int* __restrict__ pi,
          const int* __restrict__ pj,
          float4* __restrict__ out,
          int n_vec)
{
    const int base_idx = blockIdx.x * TILE + threadIdx.x;

    const int i = __ldg(pi);
    const int j = __ldg(pj);
    const uint32_t bi = (uint32_t)(NQUBIT - 1 - i);
    const uint32_t bj = (uint32_t)(NQUBIT - 1 - j);

    // Front-batch all 8 loads: 8 outstanding LDG.128 per thread.
    float4 v[VPT];
    #pragma unroll
    for (int k = 0; k < VPT; k++)
        v[k] = __ldcs(&x[base_idx + k * THREADS]);

    if (bi >= 2u && bj >= 2u) {
        // All 4 lanes of a float4 share the same (bi, bj) bits -> one sign per vec.
        #pragma unroll
        for (int k = 0; k < VPT; k++) {
            uint32_t e = ((uint32_t)(base_idx + k * THREADS) & DIM_VEC_MASK) << 2;
            uint32_t s = (((e >> bi) & (e >> bj)) & 1u) << 31;
            v[k] = xor_sign4(v[k], s);
        }
    } else {
        #pragma unroll
        for (int k = 0; k < VPT; k++)
            v[k] = apply_sign_general(v[k], (uint32_t)(base_idx + k * THREADS), bi, bj);
    }

    #pragma unroll
    for (int k = 0; k < VPT; k++)
        __stcs(&out[base_idx + k * THREADS], v[k]);
}

extern "C" void kernel_launch(void* const* d_in, const int* in_sizes, int n_in,
                              void* d_out, int out_size)
{
    const float4* x   = (const float4*)d_in[0];
    const int*    pi  = (const int*)d_in[1];
    const int*    pj  = (const int*)d_in[2];
    float4*       out = (float4*)d_out;

    const int n_vec = out_size / 4;          // 8 * 2^22 / 4 = 8388608 float4s
    const int blocks = n_vec / TILE;         // 4096, exact division
    cz_kernel<<<blocks, THREADS>>>(x, pi, pj, out, n_vec);
}